// round 11
// baseline (speedup 1.0000x reference)
#include <cuda_runtime.h>
#include <cuda_fp16.h>
#include <math.h>
#include <stdint.h>

// Problem dims
#define Tn 128
#define Bn 512
#define Dn 1024
#define Hn 128
#define G4 512   // 4*H
#define BH (Bn*Hn)

// -------- scratch (device globals: no allocations allowed) --------
__device__ float  g_pre[(size_t)Tn * Bn * G4];  // [t][b][4H]
__device__ __half g_Ah[(size_t)Bn * Tn * Dn];   // feats fp16
__device__ __half g_Wh[G4 * Dn];                // Wih1 fp16
__device__ __half g_h1h[2 * BH];                // fp16 h1 ping-pong (h1(k) -> buf k&1)
__device__ __half g_h2h[2 * BH];                // fp16 h2 ping-pong (h2(k) -> buf k&1)
__device__ unsigned g_gcnt[16 * 32];            // per-group barrier counters
__device__ unsigned g_ggen[16 * 32];            // per-group generations

// ============================================================================
// helpers
// ============================================================================
__device__ __forceinline__ uint32_t smem_u32(const void* p) {
    uint32_t a;
    asm("{ .reg .u64 t; cvta.to.shared.u64 t, %1; cvt.u32.u64 %0, t; }"
        : "=r"(a) : "l"(p));
    return a;
}

__device__ __forceinline__ void ldsm4(uint32_t* r, uint32_t addr) {
    asm volatile("ldmatrix.sync.aligned.m8n8.x4.shared.b16 {%0,%1,%2,%3}, [%4];"
                 : "=r"(r[0]), "=r"(r[1]), "=r"(r[2]), "=r"(r[3]) : "r"(addr));
}

__device__ __forceinline__ void mma16816h(float* d, const uint32_t* a, const uint32_t* b) {
    asm volatile(
        "mma.sync.aligned.m16n8k16.row.col.f32.f16.f16.f32 "
        "{%0,%1,%2,%3}, {%4,%5,%6,%7}, {%8,%9}, {%0,%1,%2,%3};"
        : "+f"(d[0]), "+f"(d[1]), "+f"(d[2]), "+f"(d[3])
        : "r"(a[0]), "r"(a[1]), "r"(a[2]), "r"(a[3]), "r"(b[0]), "r"(b[1]));
}

__device__ __forceinline__ uint4 pack8h(float4 v0, float4 v1) {
    __half2 h0 = __floats2half2_rn(v0.x, v0.y);
    __half2 h1 = __floats2half2_rn(v0.z, v0.w);
    __half2 h2 = __floats2half2_rn(v1.x, v1.y);
    __half2 h3 = __floats2half2_rn(v1.z, v1.w);
    return make_uint4(*(uint32_t*)&h0, *(uint32_t*)&h1,
                      *(uint32_t*)&h2, *(uint32_t*)&h3);
}

#define CP16(dst, src) \
    asm volatile("cp.async.cg.shared.global [%0], [%1], 16;" \
                 :: "r"(dst), "l"(src) : "memory")
#define CP_COMMIT() asm volatile("cp.async.commit_group;" ::: "memory")
#define CP_WAIT1()  asm volatile("cp.async.wait_group 1;" ::: "memory")
#define CP_WAIT0()  asm volatile("cp.async.wait_group 0;" ::: "memory")

// -------- fp32 -> fp16 bulk convert --------
__global__ void __launch_bounds__(256) cvt_fp16_kernel(
    const float* __restrict__ s, __half* __restrict__ d, int n8)
{
    int i = blockIdx.x * blockDim.x + threadIdx.x;
    int stride = gridDim.x * blockDim.x;
    for (; i < n8; i += stride) {
        const float4* sp = (const float4*)s + 2 * (size_t)i;
        *(uint4*)((char*)d + 16 * (size_t)i) = pack8h(sp[0], sp[1]);
    }
}

// ============================================================================
// pre-projection GEMM (unchanged, validated)
// ============================================================================
#define NSTG 3

__global__ void __launch_bounds__(256, 2) gemm_pre_mma(
    const __half* __restrict__ Ah,   // [65536][1024]
    const __half* __restrict__ Wh,   // [512][1024]
    const float* __restrict__ b1,    // [512]
    const float* __restrict__ b2,    // [512]
    float* __restrict__ out)         // [T][B][512]
{
    __shared__ __align__(128) char smbuf[NSTG * 16384];
    __shared__ float bias_s[128];

    const int tid  = threadIdx.x;
    const int lane = tid & 31;
    const int wid  = tid >> 5;
    const int n0 = blockIdx.x * 128;
    const int m0 = blockIdx.y * 128;
    const uint32_t sb = smem_u32(smbuf);

    if (tid < 128) bias_s[tid] = b1[n0 + tid] + b2[n0 + tid];

    const int r   = tid >> 1;
    const int u0  = (tid & 1) * 2;
    const int ssw = (r >> 1) & 3;
    const uint32_t so0 = r * 64 + (((u0)     ^ ssw) << 4);
    const uint32_t so1 = r * 64 + (((u0 + 1) ^ ssw) << 4);

    const __half* arow = Ah + (size_t)(m0 + r) * Dn;
    const __half* brow = Wh + (size_t)(n0 + r) * Dn;

    const int m0w = (wid >> 1) * 32;
    const int n0w = (wid & 1) * 64;

    const int rowA = m0w + (lane & 15);
    const int jA   = lane >> 4;
    const int swA  = (rowA >> 1) & 3;
    const uint32_t aA = sb + rowA * 64;
    const int rowB = n0w + (lane & 7) + ((lane >> 4) & 1) * 8;
    const int jB   = (lane >> 3) & 1;
    const int swB  = (rowB >> 1) & 3;
    const uint32_t aB = sb + 8192 + rowB * 64;

    float acc[2][8][4];
#pragma unroll
    for (int mi = 0; mi < 2; mi++)
#pragma unroll
        for (int ni = 0; ni < 8; ni++)
#pragma unroll
            for (int q = 0; q < 4; q++) acc[mi][ni][q] = 0.f;

    auto issue = [&](int kc, int stg) {
        const uint32_t d = sb + stg * 16384;
        const __half* as = arow + kc * 32 + u0 * 8;
        const __half* bs = brow + kc * 32 + u0 * 8;
        CP16(d + so0,        as);
        CP16(d + so1,        as + 8);
        CP16(d + 8192 + so0, bs);
        CP16(d + 8192 + so1, bs + 8);
        CP_COMMIT();
    };

    issue(0, 0);
    issue(1, 1);

#pragma unroll 1
    for (int kc = 0; kc < 32; kc++) {
        if (kc == 31) { CP_WAIT0(); } else { CP_WAIT1(); }
        __syncthreads();

        if (kc < 30) issue(kc + 2, (kc + 2) % NSTG);

        const uint32_t ba  = aA + (kc % NSTG) * 16384;
        const uint32_t bbb = aB + (kc % NSTG) * 16384;
#pragma unroll
        for (int kf = 0; kf < 2; kf++) {
            uint32_t Af[2][4], Bf[4][4];
            const int ja = (((2 * kf + jA) ^ swA) << 4);
            const int jb = (((2 * kf + jB) ^ swB) << 4);
            ldsm4(Af[0], ba + ja);
            ldsm4(Af[1], ba + 1024 + ja);
#pragma unroll
            for (int ng = 0; ng < 4; ng++)
                ldsm4(Bf[ng], bbb + ng * 1024 + jb);
#pragma unroll
            for (int mi = 0; mi < 2; mi++)
#pragma unroll
                for (int ni = 0; ni < 8; ni++)
                    mma16816h(acc[mi][ni], Af[mi], &Bf[ni >> 1][(ni & 1) * 2]);
        }
        __syncthreads();
    }

#pragma unroll
    for (int mi = 0; mi < 2; mi++) {
        int ma = m0 + m0w + mi * 16 + (lane >> 2);
        int mb = ma + 8;
        float* rowa = out + ((size_t)(ma & 127) * Bn + (ma >> 7)) * G4 + n0;
        float* rowb = out + ((size_t)(mb & 127) * Bn + (mb >> 7)) * G4 + n0;
#pragma unroll
        for (int ni = 0; ni < 8; ni++) {
            int nl = n0w + ni * 8 + (lane & 3) * 2;
            float bv0 = bias_s[nl], bv1 = bias_s[nl + 1];
            float2 v;
            v.x = acc[mi][ni][0] + bv0;
            v.y = acc[mi][ni][1] + bv1;
            *(float2*)(rowa + nl) = v;
            v.x = acc[mi][ni][2] + bv0;
            v.y = acc[mi][ni][3] + bv1;
            *(float2*)(rowb + nl) = v;
        }
    }
}

// ============================================================================
// persistent recurrence — merged-phase pipeline.
// Iteration k (after h1(k), h2(k-1) exchanged):
//   G2 = h1(k)@Wi2 + h2(k-1)@Wh2  -> cell2 -> h2(k)
//   G1 = h1(k)@W1  (+pre[k+1])    -> cell1 -> h1(k+1)     [k < 127]
// One group barrier + one h-exchange per step.
// ============================================================================
__device__ __forceinline__ float sigf(float x) {
    return __fdividef(1.f, 1.f + __expf(-x));
}
__device__ __forceinline__ float tanhfast(float x) {
    return __fmaf_rn(2.f, __fdividef(1.f, 1.f + __expf(-2.f * x)), -1.f);
}

__device__ __forceinline__ void group_barrier(int grp) {
    __syncthreads();
    if (threadIdx.x == 0) {
        const int s = grp * 32;
        __threadfence();
        unsigned gen = *(volatile unsigned*)&g_ggen[s];
        unsigned ticket = atomicAdd(&g_gcnt[s], 1);
        if (ticket == 7) {
            *(volatile unsigned*)&g_gcnt[s] = 0;
            __threadfence();
            atomicAdd(&g_ggen[s], 1);
        } else {
            while (*(volatile unsigned*)&g_ggen[s] == gen) { __nanosleep(20); }
            __threadfence();
        }
    }
    __syncthreads();
}

// SMEM byte offsets
#define ROF_W1   0          // Whh1 fp16 [64][128] swizzled, 16KB
#define ROF_WI2  16384
#define ROF_WH2  32768
#define ROF_HA   49152      // h1(k) tile [32][128] fp16 swizzled, 8KB
#define ROF_HB   57344      // h2(k-1) tile
#define ROF_G1   65536      // layer-1 gates fp32 [32][68]
#define ROF_G2   74240      // layer-2 gates fp32 [32][68]
#define ROF_PRE  82944      // pre fp32 [2][32][64] (16KB)
#define ROF_C1   99328
#define ROF_C2   101376
#define ROF_B2   103424
#define R_SMEM   103680

#define GS 68   // G row stride (floats)

__global__ void __launch_bounds__(256, 1) lstm_persist(
    const float* __restrict__ pre,    // [T][B][512]
    const float* __restrict__ Whh1,   // [512][128]
    const float* __restrict__ Wih2,   // [512][128]
    const float* __restrict__ Whh2,   // [512][128]
    const float* __restrict__ bih2,   // [512]
    const float* __restrict__ bhh2,   // [512]
    float* __restrict__ h2out)        // [B][128] (d_out)
{
    extern __shared__ char sm[];
    const uint32_t sb = smem_u32(sm);
    const int tid  = threadIdx.x;
    const int lane = tid & 31;
    const int wid  = tid >> 5;
    const int bb   = blockIdx.x >> 3;   // 0..15 (barrier group)
    const int ub   = blockIdx.x & 7;    // 0..7

    float* G1f = (float*)(sm + ROF_G1);
    float* G2f = (float*)(sm + ROF_G2);
    float* prs = (float*)(sm + ROF_PRE);
    float* c1s = (float*)(sm + ROF_C1);
    float* c2s = (float*)(sm + ROF_C2);
    float* b2s = (float*)(sm + ROF_B2);

    // ---- init: weights -> fp16 smem (swizzled), zero state ----
    for (int idx = tid; idx < 64 * 128; idx += 256) {
        int j = idx >> 7;
        int k = idx & 127;
        int gcol = ((j >> 4) << 7) + (ub << 4) + (j & 15);
        uint32_t ad = (uint32_t)(j * 256 + (((k >> 3) ^ (j & 7)) << 4) + (k & 7) * 2);
        *(__half*)(sm + ROF_W1  + ad) = __float2half(Whh1[(size_t)gcol * Hn + k]);
        *(__half*)(sm + ROF_WI2 + ad) = __float2half(Wih2[(size_t)gcol * Hn + k]);
        *(__half*)(sm + ROF_WH2 + ad) = __float2half(Whh2[(size_t)gcol * Hn + k]);
    }
    if (tid < 64) {
        int gcol = ((tid >> 4) << 7) + (ub << 4) + (tid & 15);
        b2s[tid] = bih2[gcol] + bhh2[gcol];
    }
    for (int i = tid; i < 512; i += 256) { c1s[i] = 0.f; c2s[i] = 0.f; }
    {   // zero our slices of both h2 buffers (h2(-1) read at k=0)
        int u = tid & 15;
        int bl = tid >> 4;
#pragma unroll
        for (int i = 0; i < 2; i++) {
            int row = bb * 32 + bl + i * 16;
            g_h2h[row * Hn + ub * 16 + u]      = __float2half(0.f);
            g_h2h[BH + row * Hn + ub * 16 + u] = __float2half(0.f);
        }
    }
    // prefetch pre[0] -> buf0, pre[1] -> buf1
#pragma unroll
    for (int s = 0; s < 2; s++) {
#pragma unroll
        for (int i = 0; i < 2; i++) {
            int q = 2 * tid + i;
            int b = q >> 4, ch = q & 15;
            int gcol0 = ((ch >> 2) << 7) + (ub << 4) + (ch & 3) * 4;
            const float* src = pre + ((size_t)s * Bn + bb * 32 + b) * G4 + gcol0;
            CP16(sb + ROF_PRE + (s * 2048 + b * 64 + ch * 4) * 4, src);
        }
        CP_COMMIT();
    }

    const int u2  = tid & 15;
    const int bq  = (tid >> 4) * 2;

    // ---- prologue: h1(0) from pre[0] alone (h1,c1 start at zero) ----
    CP_WAIT1();          // pre[0] done; pre[1] may fly
    __syncthreads();
#pragma unroll
    for (int i = 0; i < 2; i++) {
        int b = bq + i;
        float iv = prs[b * 64 + u2];
        float gv = prs[b * 64 + 32 + u2];
        float ov = prs[b * 64 + 48 + u2];
        float cn = sigf(iv) * tanhfast(gv);
        c1s[b * 16 + u2] = cn;
        g_h1h[(bb * 32 + b) * Hn + ub * 16 + u2] =
            __float2half(sigf(ov) * tanhfast(cn));
    }

    // ---- per-thread mma geometry (warp tile 16m x 16n; 2x4 warp grid) ----
    const int m_off = (wid >> 2) * 16;
    const int n_off = (wid & 3) * 16;
    const int rowA = m_off + (lane & 15);
    const uint32_t aoffA = rowA * 256;
    const int swA = rowA & 7;
    const int kuA0 = lane >> 4;
    const int rowB = n_off + (lane & 7) + ((lane >> 4) & 1) * 8;
    const uint32_t boffB = rowB * 256;
    const int swB = rowB & 7;
    const int kuB0 = (lane >> 3) & 1;

    auto gemm_acc = [&](uint32_t hbase, uint32_t wbase, float acc[2][4]) {
#pragma unroll
        for (int ks = 0; ks < 8; ks++) {
            uint32_t Af[4], Bf[4];
            int kuA = 2 * ks + kuA0;
            int kuB = 2 * ks + kuB0;
            ldsm4(Af, sb + hbase + aoffA + (uint32_t)(((kuA ^ swA)) << 4));
            ldsm4(Bf, sb + wbase + boffB + (uint32_t)(((kuB ^ swB)) << 4));
            mma16816h(acc[0], Af, Bf);
            mma16816h(acc[1], Af, Bf + 2);
        }
    };
    auto stage_G = [&](float* Gdst, float acc[2][4]) {
        int r0 = m_off + (lane >> 2);
        int c0 = n_off + 2 * (lane & 3);
#pragma unroll
        for (int h = 0; h < 2; h++) {
            Gdst[r0 * GS + c0 + 8 * h]           = acc[h][0];
            Gdst[r0 * GS + c0 + 8 * h + 1]       = acc[h][1];
            Gdst[(r0 + 8) * GS + c0 + 8 * h]     = acc[h][2];
            Gdst[(r0 + 8) * GS + c0 + 8 * h + 1] = acc[h][3];
        }
    };

#pragma unroll 1
    for (int k = 0; k < Tn; k++) {
        const int pa = k & 1;
        group_barrier(bb);   // h1(k) in g_h1h[pa], h2(k-1) in g_h2h[pa^1] visible

        // exchange: hA <- h1(k), hB <- h2(k-1)
        {
            const __half* h1src = g_h1h + pa * BH;
            const __half* h2src = g_h2h + (pa ^ 1) * BH;
#pragma unroll
            for (int i = 0; i < 2; i++) {
                int q = 2 * tid + i;
                int rr = q >> 4, ku = q & 15;
                uint32_t doff = (uint32_t)(rr * 256 + ((ku ^ (rr & 7)) << 4));
                CP16(sb + ROF_HA + doff, h1src + (bb * 32 + rr) * Hn + ku * 8);
                CP16(sb + ROF_HB + doff, h2src + (bb * 32 + rr) * Hn + ku * 8);
            }
            CP_COMMIT();
        }
        if (k < Tn - 2) {   // prefetch pre[k+2] into buf k&1 (stays in flight)
#pragma unroll
            for (int i = 0; i < 2; i++) {
                int q = 2 * tid + i;
                int b = q >> 4, ch = q & 15;
                int gcol0 = ((ch >> 2) << 7) + (ub << 4) + (ch & 3) * 4;
                const float* src = pre + ((size_t)(k + 2) * Bn + bb * 32 + b) * G4 + gcol0;
                CP16(sb + ROF_PRE + (pa * 2048 + b * 64 + ch * 4) * 4, src);
            }
            CP_COMMIT();
            CP_WAIT1();
        } else {
            CP_WAIT0();
        }
        __syncthreads();

        // three GEMMs in one region
        {
            float acc2[2][4], accA[2][4];
#pragma unroll
            for (int q = 0; q < 2; q++)
#pragma unroll
                for (int w = 0; w < 4; w++) { acc2[q][w] = 0.f; accA[q][w] = 0.f; }
            gemm_acc(ROF_HA, ROF_WI2, acc2);
            gemm_acc(ROF_HB, ROF_WH2, acc2);
            if (k < Tn - 1) gemm_acc(ROF_HA, ROF_W1, accA);
            stage_G(G2f, acc2);
            if (k < Tn - 1) stage_G(G1f, accA);
        }
        __syncthreads();

        // cell2: time k  -> h2(k) into g_h2h[pa]  (or d_out at k=127)
        __half* h2dst = g_h2h + pa * BH;
#pragma unroll
        for (int i = 0; i < 2; i++) {
            int b = bq + i;
            float iv = G2f[b * GS + u2]      + b2s[u2];
            float fv = G2f[b * GS + 16 + u2] + b2s[16 + u2];
            float gv = G2f[b * GS + 32 + u2] + b2s[32 + u2];
            float ov = G2f[b * GS + 48 + u2] + b2s[48 + u2];
            int ci = b * 16 + u2;
            float cp = c2s[ci];
            float cn = sigf(fv) * cp + sigf(iv) * tanhfast(gv);
            c2s[ci] = cn;
            float hn = sigf(ov) * tanhfast(cn);
            if (k == Tn - 1)
                h2out[(bb * 32 + b) * Hn + ub * 16 + u2] = hn;
            else
                h2dst[(bb * 32 + b) * Hn + ub * 16 + u2] = __float2half(hn);
        }
        // cell1: time k+1 -> h1(k+1) into g_h1h[pa^1]
        if (k < Tn - 1) {
            const float* presc = prs + ((k + 1) & 1) * 2048;
            __half* h1dst = g_h1h + (pa ^ 1) * BH;
#pragma unroll
            for (int i = 0; i < 2; i++) {
                int b = bq + i;
                float iv = G1f[b * GS + u2]      + presc[b * 64 + u2];
                float fv = G1f[b * GS + 16 + u2] + presc[b * 64 + 16 + u2];
                float gv = G1f[b * GS + 32 + u2] + presc[b * 64 + 32 + u2];
                float ov = G1f[b * GS + 48 + u2] + presc[b * 64 + 48 + u2];
                int ci = b * 16 + u2;
                float cp = c1s[ci];
                float cn = sigf(fv) * cp + sigf(iv) * tanhfast(gv);
                c1s[ci] = cn;
                h1dst[(bb * 32 + b) * Hn + ub * 16 + u2] =
                    __float2half(sigf(ov) * tanhfast(cn));
            }
        }
        // next iteration's barrier (starts with __syncthreads) provides the
        // intra-CTA ordering before smem buffers are reused.
    }
}

// -------- launch --------
extern "C" void kernel_launch(void* const* d_in, const int* in_sizes, int n_in,
                              void* d_out, int out_size) {
    const float* feats = (const float*)d_in[0];
    const float* Wih1  = (const float*)d_in[1];
    const float* Whh1  = (const float*)d_in[2];
    const float* bih1  = (const float*)d_in[3];
    const float* bhh1  = (const float*)d_in[4];
    const float* Wih2  = (const float*)d_in[5];
    const float* Whh2  = (const float*)d_in[6];
    const float* bih2  = (const float*)d_in[7];
    const float* bhh2  = (const float*)d_in[8];

    float* pre;
    __half *Ah, *Wh;
    cudaGetSymbolAddress((void**)&pre, g_pre);
    cudaGetSymbolAddress((void**)&Ah,  g_Ah);
    cudaGetSymbolAddress((void**)&Wh,  g_Wh);

    static int attr_set = 0;
    if (!attr_set) {
        cudaFuncSetAttribute(lstm_persist,
                             cudaFuncAttributeMaxDynamicSharedMemorySize,
                             R_SMEM);
        attr_set = 1;
    }

    // fp32 -> fp16 staging
    cvt_fp16_kernel<<<4096, 256>>>(feats, Ah, (Bn * Tn * Dn) / 8);
    cvt_fp16_kernel<<<256, 256>>>(Wih1, Wh, (G4 * Dn) / 8);

    // pre = feats @ Wih1^T + bih1 + bhh1
    gemm_pre_mma<<<dim3(4, 512), 256>>>(Ah, Wh, bih1, bhh1, pre);

    lstm_persist<<<128, 256, R_SMEM>>>(
        pre, Whh1, Wih2, Whh2, bih2, bhh2, (float*)d_out);
}

// round 12
// speedup vs baseline: 1.3156x; 1.3156x over previous
#include <cuda_runtime.h>
#include <cuda_fp16.h>
#include <math.h>
#include <stdint.h>

// Problem dims
#define Tn 128
#define Bn 512
#define Dn 1024
#define Hn 128
#define G4 512   // 4*H

// -------- scratch (device globals: no allocations allowed) --------
__device__ float  g_pre[(size_t)Tn * Bn * G4];  // [t][b][4H]
__device__ __half g_Ah[(size_t)Bn * Tn * Dn];   // feats fp16
__device__ __half g_Wh[G4 * Dn];                // Wih1 fp16

// ============================================================================
// helpers
// ============================================================================
__device__ __forceinline__ uint32_t smem_u32(const void* p) {
    uint32_t a;
    asm("{ .reg .u64 t; cvta.to.shared.u64 t, %1; cvt.u32.u64 %0, t; }"
        : "=r"(a) : "l"(p));
    return a;
}

__device__ __forceinline__ void ldsm4(uint32_t* r, uint32_t addr) {
    asm volatile("ldmatrix.sync.aligned.m8n8.x4.shared.b16 {%0,%1,%2,%3}, [%4];"
                 : "=r"(r[0]), "=r"(r[1]), "=r"(r[2]), "=r"(r[3]) : "r"(addr));
}

__device__ __forceinline__ void mma16816h(float* d, const uint32_t* a, const uint32_t* b) {
    asm volatile(
        "mma.sync.aligned.m16n8k16.row.col.f32.f16.f16.f32 "
        "{%0,%1,%2,%3}, {%4,%5,%6,%7}, {%8,%9}, {%0,%1,%2,%3};"
        : "+f"(d[0]), "+f"(d[1]), "+f"(d[2]), "+f"(d[3])
        : "r"(a[0]), "r"(a[1]), "r"(a[2]), "r"(a[3]), "r"(b[0]), "r"(b[1]));
}

__device__ __forceinline__ uint4 pack8h(float4 v0, float4 v1) {
    __half2 h0 = __floats2half2_rn(v0.x, v0.y);
    __half2 h1 = __floats2half2_rn(v0.z, v0.w);
    __half2 h2 = __floats2half2_rn(v1.x, v1.y);
    __half2 h3 = __floats2half2_rn(v1.z, v1.w);
    return make_uint4(*(uint32_t*)&h0, *(uint32_t*)&h1,
                      *(uint32_t*)&h2, *(uint32_t*)&h3);
}

#define CP16(dst, src) \
    asm volatile("cp.async.cg.shared.global [%0], [%1], 16;" \
                 :: "r"(dst), "l"(src) : "memory")
#define CP_COMMIT() asm volatile("cp.async.commit_group;" ::: "memory")
#define CP_WAIT1()  asm volatile("cp.async.wait_group 1;" ::: "memory")
#define CP_WAIT0()  asm volatile("cp.async.wait_group 0;" ::: "memory")

#define CLUSTER_SYNC() do { \
    asm volatile("barrier.cluster.arrive.aligned;" ::: "memory"); \
    asm volatile("barrier.cluster.wait.aligned;" ::: "memory"); \
} while (0)

// -------- fp32 -> fp16 bulk convert --------
__global__ void __launch_bounds__(256) cvt_fp16_kernel(
    const float* __restrict__ s, __half* __restrict__ d, int n8)
{
    int i = blockIdx.x * blockDim.x + threadIdx.x;
    int stride = gridDim.x * blockDim.x;
    for (; i < n8; i += stride) {
        const float4* sp = (const float4*)s + 2 * (size_t)i;
        *(uint4*)((char*)d + 16 * (size_t)i) = pack8h(sp[0], sp[1]);
    }
}

// ============================================================================
// pre-projection GEMM (unchanged, validated)
// ============================================================================
#define NSTG 3

__global__ void __launch_bounds__(256, 2) gemm_pre_mma(
    const __half* __restrict__ Ah,   // [65536][1024]
    const __half* __restrict__ Wh,   // [512][1024]
    const float* __restrict__ b1,    // [512]
    const float* __restrict__ b2,    // [512]
    float* __restrict__ out)         // [T][B][512]
{
    __shared__ __align__(128) char smbuf[NSTG * 16384];
    __shared__ float bias_s[128];

    const int tid  = threadIdx.x;
    const int lane = tid & 31;
    const int wid  = tid >> 5;
    const int n0 = blockIdx.x * 128;
    const int m0 = blockIdx.y * 128;
    const uint32_t sb = smem_u32(smbuf);

    if (tid < 128) bias_s[tid] = b1[n0 + tid] + b2[n0 + tid];

    const int r   = tid >> 1;
    const int u0  = (tid & 1) * 2;
    const int ssw = (r >> 1) & 3;
    const uint32_t so0 = r * 64 + (((u0)     ^ ssw) << 4);
    const uint32_t so1 = r * 64 + (((u0 + 1) ^ ssw) << 4);

    const __half* arow = Ah + (size_t)(m0 + r) * Dn;
    const __half* brow = Wh + (size_t)(n0 + r) * Dn;

    const int m0w = (wid >> 1) * 32;
    const int n0w = (wid & 1) * 64;

    const int rowA = m0w + (lane & 15);
    const int jA   = lane >> 4;
    const int swA  = (rowA >> 1) & 3;
    const uint32_t aA = sb + rowA * 64;
    const int rowB = n0w + (lane & 7) + ((lane >> 4) & 1) * 8;
    const int jB   = (lane >> 3) & 1;
    const int swB  = (rowB >> 1) & 3;
    const uint32_t aB = sb + 8192 + rowB * 64;

    float acc[2][8][4];
#pragma unroll
    for (int mi = 0; mi < 2; mi++)
#pragma unroll
        for (int ni = 0; ni < 8; ni++)
#pragma unroll
            for (int q = 0; q < 4; q++) acc[mi][ni][q] = 0.f;

    auto issue = [&](int kc, int stg) {
        const uint32_t d = sb + stg * 16384;
        const __half* as = arow + kc * 32 + u0 * 8;
        const __half* bs = brow + kc * 32 + u0 * 8;
        CP16(d + so0,        as);
        CP16(d + so1,        as + 8);
        CP16(d + 8192 + so0, bs);
        CP16(d + 8192 + so1, bs + 8);
        CP_COMMIT();
    };

    issue(0, 0);
    issue(1, 1);

#pragma unroll 1
    for (int kc = 0; kc < 32; kc++) {
        if (kc == 31) { CP_WAIT0(); } else { CP_WAIT1(); }
        __syncthreads();

        if (kc < 30) issue(kc + 2, (kc + 2) % NSTG);

        const uint32_t ba  = aA + (kc % NSTG) * 16384;
        const uint32_t bbb = aB + (kc % NSTG) * 16384;
#pragma unroll
        for (int kf = 0; kf < 2; kf++) {
            uint32_t Af[2][4], Bf[4][4];
            const int ja = (((2 * kf + jA) ^ swA) << 4);
            const int jb = (((2 * kf + jB) ^ swB) << 4);
            ldsm4(Af[0], ba + ja);
            ldsm4(Af[1], ba + 1024 + ja);
#pragma unroll
            for (int ng = 0; ng < 4; ng++)
                ldsm4(Bf[ng], bbb + ng * 1024 + jb);
#pragma unroll
            for (int mi = 0; mi < 2; mi++)
#pragma unroll
                for (int ni = 0; ni < 8; ni++)
                    mma16816h(acc[mi][ni], Af[mi], &Bf[ni >> 1][(ni & 1) * 2]);
        }
        __syncthreads();
    }

#pragma unroll
    for (int mi = 0; mi < 2; mi++) {
        int ma = m0 + m0w + mi * 16 + (lane >> 2);
        int mb = ma + 8;
        float* rowa = out + ((size_t)(ma & 127) * Bn + (ma >> 7)) * G4 + n0;
        float* rowb = out + ((size_t)(mb & 127) * Bn + (mb >> 7)) * G4 + n0;
#pragma unroll
        for (int ni = 0; ni < 8; ni++) {
            int nl = n0w + ni * 8 + (lane & 3) * 2;
            float bv0 = bias_s[nl], bv1 = bias_s[nl + 1];
            float2 v;
            v.x = acc[mi][ni][0] + bv0;
            v.y = acc[mi][ni][1] + bv1;
            *(float2*)(rowa + nl) = v;
            v.x = acc[mi][ni][2] + bv0;
            v.y = acc[mi][ni][3] + bv1;
            *(float2*)(rowb + nl) = v;
        }
    }
}

// ============================================================================
// persistent recurrence — 8-CTA clusters, DSMEM h-exchange.
// Grid 128 = 16 clusters x 8 CTAs. CTA rank ub = blockIdx.x & 7 owns units
// ub*16..+16 (all 4 gates) for batch rows bb*32..+32.
// Per step t (r10 two-phase schedule):
//   A: G1 = hA[p]@W1 (+pre[t]) -> cell1 -> scatter h1(t) into all peers' hA[p^1]
//      CLUSTER_SYNC
//   B: G2 = hA[p^1]@Wi2 + hB[p]@Wh2 (+b2) -> cell2 -> scatter h2(t) -> hB[p^1]
//      CLUSTER_SYNC
// ============================================================================
__device__ __forceinline__ float sigf(float x) {
    return __fdividef(1.f, 1.f + __expf(-x));
}
__device__ __forceinline__ float tanhfast(float x) {
    return __fmaf_rn(2.f, __fdividef(1.f, 1.f + __expf(-2.f * x)), -1.f);
}

// SMEM byte offsets
#define ROF_W1   0          // Whh1 fp16 [64][128] swizzled, 16KB
#define ROF_WI2  16384
#define ROF_WH2  32768
#define ROF_HA   49152      // h1 tile, 2 bufs x 8KB
#define ROF_HB   65536      // h2 tile, 2 bufs x 8KB
#define ROF_G    81920      // gates fp32 [32][68] = 8704
#define ROF_PRE  90624      // pre fp32 [2][32][64] = 16384
#define ROF_STG  107008     // scatter staging [32][16] half = 1024
#define ROF_C1   108032
#define ROF_C2   110080
#define ROF_B2   112128
#define R_SMEM   112384

#define GS 68   // G row stride (floats)

__global__ void __launch_bounds__(256, 1) __cluster_dims__(8, 1, 1)
lstm_persist(
    const float* __restrict__ pre,    // [T][B][512]
    const float* __restrict__ Whh1,   // [512][128]
    const float* __restrict__ Wih2,   // [512][128]
    const float* __restrict__ Whh2,   // [512][128]
    const float* __restrict__ bih2,   // [512]
    const float* __restrict__ bhh2,   // [512]
    float* __restrict__ h2out)        // [B][128] (d_out)
{
    extern __shared__ char sm[];
    const uint32_t sb = smem_u32(sm);
    const int tid  = threadIdx.x;
    const int lane = tid & 31;
    const int wid  = tid >> 5;
    const int bb   = blockIdx.x >> 3;   // cluster id 0..15
    const int ub   = blockIdx.x & 7;    // rank in cluster

    float* Gf  = (float*)(sm + ROF_G);
    float* prs = (float*)(sm + ROF_PRE);
    float* c1s = (float*)(sm + ROF_C1);
    float* c2s = (float*)(sm + ROF_C2);
    float* b2s = (float*)(sm + ROF_B2);
    __half* stg = (__half*)(sm + ROF_STG);

    // ---- init: weights -> fp16 smem (swizzled), biases, zero state ----
    for (int idx = tid; idx < 64 * 128; idx += 256) {
        int j = idx >> 7;
        int k = idx & 127;
        int gcol = ((j >> 4) << 7) + (ub << 4) + (j & 15);
        uint32_t ad = (uint32_t)(j * 256 + (((k >> 3) ^ (j & 7)) << 4) + (k & 7) * 2);
        *(__half*)(sm + ROF_W1  + ad) = __float2half(Whh1[(size_t)gcol * Hn + k]);
        *(__half*)(sm + ROF_WI2 + ad) = __float2half(Wih2[(size_t)gcol * Hn + k]);
        *(__half*)(sm + ROF_WH2 + ad) = __float2half(Whh2[(size_t)gcol * Hn + k]);
    }
    if (tid < 64) {
        int gcol = ((tid >> 4) << 7) + (ub << 4) + (tid & 15);
        b2s[tid] = bih2[gcol] + bhh2[gcol];
    }
    for (int i = tid; i < 512; i += 256) { c1s[i] = 0.f; c2s[i] = 0.f; }
    // zero hA[0], hB[0] (inputs at t=0)
    for (int i = tid; i < 2048; i += 256) {
        ((uint32_t*)(sm + ROF_HA))[i] = 0;
        ((uint32_t*)(sm + ROF_HB))[i] = 0;
    }
    // prefetch pre[0] -> buf0
    {
#pragma unroll
        for (int i = 0; i < 2; i++) {
            int q = 2 * tid + i;
            int b = q >> 4, ch = q & 15;
            int gcol0 = ((ch >> 2) << 7) + (ub << 4) + (ch & 3) * 4;
            const float* src = pre + ((size_t)(bb * 32 + b)) * G4 + gcol0;
            CP16(sb + ROF_PRE + (b * 64 + ch * 4) * 4, src);
        }
        CP_COMMIT();
    }

    // ---- scatter geometry: thread handles 2 of 512 (dest,chunk) pairs ----
    // global pair g = tid*2 + j ; dest rank d = g>>6 ; rem = g&63 ;
    // row rr = rem>>1 ; kq = rem&1 (two 16B chunks per row from this CTA)
    const int g0 = tid * 2, g1 = g0 + 1;
    const int d0 = g0 >> 6, d1 = g1 >> 6;
    uint32_t pb0, pb1;
    asm("mapa.shared::cluster.u32 %0, %1, %2;" : "=r"(pb0) : "r"(sb), "r"(d0));
    asm("mapa.shared::cluster.u32 %0, %1, %2;" : "=r"(pb1) : "r"(sb), "r"(d1));
    const int rr0 = (g0 & 63) >> 1, kq0 = g0 & 1;
    const int rr1 = (g1 & 63) >> 1, kq1 = g1 & 1;
    const uint32_t dof0 = (uint32_t)(rr0 * 256 + (((2 * ub + kq0) ^ (rr0 & 7)) << 4));
    const uint32_t dof1 = (uint32_t)(rr1 * 256 + (((2 * ub + kq1) ^ (rr1 & 7)) << 4));
    const uint32_t sof0 = (uint32_t)(rr0 * 32 + kq0 * 16);
    const uint32_t sof1 = (uint32_t)(rr1 * 32 + kq1 * 16);

    auto scatter = [&](uint32_t regionOff) {
        uint4 v0 = *(const uint4*)(sm + ROF_STG + sof0);
        uint4 v1 = *(const uint4*)(sm + ROF_STG + sof1);
        asm volatile("st.shared::cluster.v4.b32 [%0], {%1,%2,%3,%4};"
                     :: "r"(pb0 + regionOff + dof0),
                        "r"(v0.x), "r"(v0.y), "r"(v0.z), "r"(v0.w) : "memory");
        asm volatile("st.shared::cluster.v4.b32 [%0], {%1,%2,%3,%4};"
                     :: "r"(pb1 + regionOff + dof1),
                        "r"(v1.x), "r"(v1.y), "r"(v1.z), "r"(v1.w) : "memory");
    };

    CLUSTER_SYNC();   // init complete cluster-wide

    // ---- mma geometry (warp tile 16m x 16n; 2x4 warp grid) ----
    const int m_off = (wid >> 2) * 16;
    const int n_off = (wid & 3) * 16;
    const int rowA = m_off + (lane & 15);
    const uint32_t aoffA = rowA * 256;
    const int swA = rowA & 7;
    const int kuA0 = lane >> 4;
    const int rowB = n_off + (lane & 7) + ((lane >> 4) & 1) * 8;
    const uint32_t boffB = rowB * 256;
    const int swB = rowB & 7;
    const int kuB0 = (lane >> 3) & 1;

    const int u2 = tid & 15;
    const int bq = (tid >> 4) * 2;

    auto gemm_acc = [&](uint32_t hbase, uint32_t wbase, float acc[2][4]) {
#pragma unroll
        for (int ks = 0; ks < 8; ks++) {
            uint32_t Af[4], Bf[4];
            int kuA = 2 * ks + kuA0;
            int kuB = 2 * ks + kuB0;
            ldsm4(Af, sb + hbase + aoffA + (uint32_t)(((kuA ^ swA)) << 4));
            ldsm4(Bf, sb + wbase + boffB + (uint32_t)(((kuB ^ swB)) << 4));
            mma16816h(acc[0], Af, Bf);
            mma16816h(acc[1], Af, Bf + 2);
        }
    };
    auto stage_G = [&](float acc[2][4]) {
        int r0 = m_off + (lane >> 2);
        int c0 = n_off + 2 * (lane & 3);
#pragma unroll
        for (int h = 0; h < 2; h++) {
            Gf[r0 * GS + c0 + 8 * h]           = acc[h][0];
            Gf[r0 * GS + c0 + 8 * h + 1]       = acc[h][1];
            Gf[(r0 + 8) * GS + c0 + 8 * h]     = acc[h][2];
            Gf[(r0 + 8) * GS + c0 + 8 * h + 1] = acc[h][3];
        }
    };

#pragma unroll 1
    for (int t = 0; t < Tn; t++) {
        const int pa = t & 1;
        const uint32_t hAcur = ROF_HA + pa * 8192;
        const uint32_t hAnxt = ROF_HA + (pa ^ 1) * 8192;
        const uint32_t hBcur = ROF_HB + pa * 8192;
        const uint32_t hBnxt = ROF_HB + (pa ^ 1) * 8192;

        // ===== Phase A: layer-1 =====
        {
            float acc[2][4];
#pragma unroll
            for (int q = 0; q < 2; q++)
#pragma unroll
                for (int w = 0; w < 4; w++) acc[q][w] = 0.f;
            gemm_acc(hAcur, ROF_W1, acc);
            stage_G(acc);
        }
        // prefetch pre[t+1]; ensure pre[t] landed
        if (t < Tn - 1) {
#pragma unroll
            for (int i = 0; i < 2; i++) {
                int q = 2 * tid + i;
                int b = q >> 4, ch = q & 15;
                int gcol0 = ((ch >> 2) << 7) + (ub << 4) + (ch & 3) * 4;
                const float* src = pre + ((size_t)(t + 1) * Bn + bb * 32 + b) * G4 + gcol0;
                CP16(sb + ROF_PRE + (((t + 1) & 1) * 2048 + b * 64 + ch * 4) * 4, src);
            }
            CP_COMMIT();
            CP_WAIT1();
        } else {
            CP_WAIT0();
        }
        __syncthreads();   // G1 staged + pre[t] visible

        // cell1 -> staging
        {
            const float* presc = prs + pa * 2048;
#pragma unroll
            for (int i = 0; i < 2; i++) {
                int b = bq + i;
                float iv = Gf[b * GS + u2]      + presc[b * 64 + u2];
                float fv = Gf[b * GS + 16 + u2] + presc[b * 64 + 16 + u2];
                float gv = Gf[b * GS + 32 + u2] + presc[b * 64 + 32 + u2];
                float ov = Gf[b * GS + 48 + u2] + presc[b * 64 + 48 + u2];
                int ci = b * 16 + u2;
                float cp = c1s[ci];
                float cn = sigf(fv) * cp + sigf(iv) * tanhfast(gv);
                c1s[ci] = cn;
                stg[b * 16 + u2] = __float2half(sigf(ov) * tanhfast(cn));
            }
        }
        __syncthreads();   // staging complete
        scatter(hAnxt);    // h1(t) -> all peers (incl. self)
        CLUSTER_SYNC();    // hA[pa^1] complete everywhere

        // ===== Phase B: layer-2 =====
        {
            float acc[2][4];
#pragma unroll
            for (int q = 0; q < 2; q++)
#pragma unroll
                for (int w = 0; w < 4; w++) acc[q][w] = 0.f;
            gemm_acc(hAnxt, ROF_WI2, acc);
            gemm_acc(hBcur, ROF_WH2, acc);
            stage_G(acc);
        }
        __syncthreads();

        if (t == Tn - 1) {
            // final step: write fp32 output, no scatter needed
#pragma unroll
            for (int i = 0; i < 2; i++) {
                int b = bq + i;
                float iv = Gf[b * GS + u2]      + b2s[u2];
                float fv = Gf[b * GS + 16 + u2] + b2s[16 + u2];
                float gv = Gf[b * GS + 32 + u2] + b2s[32 + u2];
                float ov = Gf[b * GS + 48 + u2] + b2s[48 + u2];
                int ci = b * 16 + u2;
                float cp = c2s[ci];
                float cn = sigf(fv) * cp + sigf(iv) * tanhfast(gv);
                float hn = sigf(ov) * tanhfast(cn);
                h2out[(bb * 32 + b) * Hn + ub * 16 + u2] = hn;
            }
        } else {
#pragma unroll
            for (int i = 0; i < 2; i++) {
                int b = bq + i;
                float iv = Gf[b * GS + u2]      + b2s[u2];
                float fv = Gf[b * GS + 16 + u2] + b2s[16 + u2];
                float gv = Gf[b * GS + 32 + u2] + b2s[32 + u2];
                float ov = Gf[b * GS + 48 + u2] + b2s[48 + u2];
                int ci = b * 16 + u2;
                float cp = c2s[ci];
                float cn = sigf(fv) * cp + sigf(iv) * tanhfast(gv);
                c2s[ci] = cn;
                stg[b * 16 + u2] = __float2half(sigf(ov) * tanhfast(cn));
            }
            __syncthreads();   // staging complete
            scatter(hBnxt);    // h2(t) -> all peers
            CLUSTER_SYNC();    // hB[pa^1] complete; also orders buffer reuse
        }
    }
}

// -------- launch --------
extern "C" void kernel_launch(void* const* d_in, const int* in_sizes, int n_in,
                              void* d_out, int out_size) {
    const float* feats = (const float*)d_in[0];
    const float* Wih1  = (const float*)d_in[1];
    const float* Whh1  = (const float*)d_in[2];
    const float* bih1  = (const float*)d_in[3];
    const float* bhh1  = (const float*)d_in[4];
    const float* Wih2  = (const float*)d_in[5];
    const float* Whh2  = (const float*)d_in[6];
    const float* bih2  = (const float*)d_in[7];
    const float* bhh2  = (const float*)d_in[8];

    float* pre;
    __half *Ah, *Wh;
    cudaGetSymbolAddress((void**)&pre, g_pre);
    cudaGetSymbolAddress((void**)&Ah,  g_Ah);
    cudaGetSymbolAddress((void**)&Wh,  g_Wh);

    static int attr_set = 0;
    if (!attr_set) {
        cudaFuncSetAttribute(lstm_persist,
                             cudaFuncAttributeMaxDynamicSharedMemorySize,
                             R_SMEM);
        attr_set = 1;
    }

    // fp32 -> fp16 staging
    cvt_fp16_kernel<<<4096, 256>>>(feats, Ah, (Bn * Tn * Dn) / 8);
    cvt_fp16_kernel<<<256, 256>>>(Wih1, Wh, (G4 * Dn) / 8);

    // pre = feats @ Wih1^T + bih1 + bhh1
    gemm_pre_mma<<<dim3(4, 512), 256>>>(Ah, Wh, bih1, bhh1, pre);

    lstm_persist<<<128, 256, R_SMEM>>>(
        pre, Whh1, Wih2, Whh2, bih2, bhh2, (float*)d_out);
}